// round 5
// baseline (speedup 1.0000x reference)
#include <cuda_runtime.h>
#include <math.h>

#define N_NODES 5000
#define DEG 16
#define S 17
#define T 10
#define MN 10
#define D 128
#define EPS 0.1f
#define N_OUTER 3
#define N_SINK 5
#define TM 100
#define NPB 10
#define LOG2E 1.4426950408889634f
#define FULLMASK 0xffffffffu

__device__ __forceinline__ float ex2(float x) {
    float r; asm("ex2.approx.ftz.f32 %0, %1;" : "=f"(r) : "f"(x)); return r;
}

// ---------------- device-global precomputed state / scratch ----------------
__device__ float g_alpha;
__device__ float g_C2[T*MN*MN];     // softmax(templates, axis=1) [t][l][k]
__device__ float g_q[T*MN];
__device__ float g_hC2[T*MN];       // sum_k C2[t,l,k]^2 q[t,k]
__device__ float g_Hq[T*MN];        // sum_k q[t,k] C2[t,l,k]
__device__ float g_f2sq[T*MN];      // ||F2[t,m]||^2
__device__ float g_Pm[(size_t)N_NODES * TM];  // -2<x_n,F2_tm> only
__device__ float g_xsq[N_NODES];

// ---------------- kernel 1: fused Pm GEMM + tiny precompute (block 0) ------
__global__ __launch_bounds__(256) void pm_pre_kernel(const float* __restrict__ x,
                                                     const float* __restrict__ tf,
                                                     const float* __restrict__ tmpl,
                                                     const float* __restrict__ q0,
                                                     const float* __restrict__ alpha0) {
    __shared__ __align__(16) float4 sx4[NPB][D/4];
    int base = blockIdx.x * NPB;
    int tid = threadIdx.x;

    for (int idx = tid; idx < NPB*(D/4); idx += 256) {
        int r = idx / (D/4), c = idx % (D/4);
        sx4[r][c] = ((const float4*)(x + (size_t)(base + r)*D))[c];
    }
    __syncthreads();
    if (tid < NPB) {
        float s = 0.f;
        #pragma unroll 8
        for (int d = 0; d < D/4; d++) {
            float4 v = sx4[tid][d];
            s += v.x*v.x + v.y*v.y + v.z*v.z + v.w*v.w;
        }
        g_xsq[base + tid] = s;
    }
    if (tid < NPB * (TM/4)) {
        int nl = tid % NPB, tm0 = (tid / NPB) * 4;
        const float4* b0 = (const float4*)(tf + (size_t)(tm0+0)*D);
        const float4* b1 = (const float4*)(tf + (size_t)(tm0+1)*D);
        const float4* b2 = (const float4*)(tf + (size_t)(tm0+2)*D);
        const float4* b3 = (const float4*)(tf + (size_t)(tm0+3)*D);
        float a0=0.f, a1=0.f, a2=0.f, a3=0.f;
        #pragma unroll 8
        for (int d = 0; d < D/4; d++) {
            float4 av = sx4[nl][d];
            float4 r0 = b0[d], r1 = b1[d], r2 = b2[d], r3 = b3[d];
            a0 += av.x*r0.x + av.y*r0.y + av.z*r0.z + av.w*r0.w;
            a1 += av.x*r1.x + av.y*r1.y + av.z*r1.z + av.w*r1.w;
            a2 += av.x*r2.x + av.y*r2.y + av.z*r2.z + av.w*r2.w;
            a3 += av.x*r3.x + av.y*r3.y + av.z*r3.z + av.w*r3.w;
        }
        size_t o = (size_t)(base + nl)*TM + tm0;
        g_Pm[o+0] = -2.f*a0; g_Pm[o+1] = -2.f*a1;
        g_Pm[o+2] = -2.f*a2; g_Pm[o+3] = -2.f*a3;
    }

    if (blockIdx.x == 0) {
        if (tid == 0) g_alpha = 1.0f / (1.0f + expf(-alpha0[0]));
        if (tid < T) {
            float mx = -1e30f;
            for (int m = 0; m < MN; m++) mx = fmaxf(mx, q0[tid*MN + m]);
            float s = 0.f, e[MN];
            for (int m = 0; m < MN; m++) { e[m] = expf(q0[tid*MN + m] - mx); s += e[m]; }
            for (int m = 0; m < MN; m++) g_q[tid*MN + m] = e[m] / s;
        }
        if (tid < T*MN) {
            int t = tid / MN, j = tid % MN;
            float mx = -1e30f;
            for (int i = 0; i < MN; i++) mx = fmaxf(mx, tmpl[(t*MN + i)*MN + j]);
            float s = 0.f, e[MN];
            for (int i = 0; i < MN; i++) { e[i] = expf(tmpl[(t*MN + i)*MN + j] - mx); s += e[i]; }
            for (int i = 0; i < MN; i++) g_C2[(t*MN + i)*MN + j] = e[i] / s;
        }
        if (tid < T*MN) {
            float s = 0.f;
            const float4* row = (const float4*)(tf + (size_t)tid * D);
            #pragma unroll 8
            for (int d = 0; d < D/4; d++) {
                float4 v = row[d];
                s += v.x*v.x + v.y*v.y + v.z*v.z + v.w*v.w;
            }
            g_f2sq[tid] = s;
        }
        __syncthreads();
        if (tid < T*MN) {
            int t = tid / MN, l = tid % MN;
            float s = 0.f, hq = 0.f;
            for (int k = 0; k < MN; k++) {
                float c = g_C2[(t*MN + l)*MN + k];
                float qq = g_q[t*MN + k];
                s += c * c * qq;
                hq += c * qq;
            }
            g_hC2[tid] = s;
            g_Hq[tid]  = hq;
        }
    }
}

// ---------------- kernel 2: FGW, H0-only + smem-broadcast Sinkhorn ---------
__global__ __launch_bounds__(320, 3) void ltfgw_kernel(const int* __restrict__ dst,
                                                       float* __restrict__ out) {
    __shared__ __align__(16) float sC2[T][MN][12];   // zero-padded rows
    __shared__ __align__(16) float ktbuf[T][MN][20]; // K transposed, pad 20
    __shared__ __align__(16) float vbuf[T][12];
    __shared__ __align__(16) float wbuf[T][20];
    __shared__ __align__(16) float gbuf[T][12];
    __shared__ __align__(16) float h0buf[T][12];
    __shared__ float sHq[T][MN];
    __shared__ float shC2[T][MN];
    __shared__ float sF2[T][MN];
    __shared__ unsigned smask[S];
    __shared__ int ids[S];

    int n = blockIdx.x, tid = threadIdx.x;

    if (tid < S) {
        ids[tid] = (tid == 0) ? n : dst[n*DEG + tid - 1];
        smask[tid] = 0u;
    }
    for (int idx = tid; idx < T*MN*12; idx += 320) {
        int t0 = idx / (MN*12), rem = idx % (MN*12);
        int l0 = rem / 12, k0 = rem % 12;
        ((float*)sC2)[idx] = (k0 < MN) ? g_C2[(t0*MN + l0)*MN + k0] : 0.f;
    }
    for (int idx = tid; idx < T*MN; idx += 320) {
        ((float*)sHq)[idx]  = g_Hq[idx];
        ((float*)shC2)[idx] = g_hC2[idx];
        ((float*)sF2)[idx]  = g_f2sq[idx];
    }
    __syncthreads();

    for (int e = tid; e < S*DEG; e += 320) {
        int a = e / DEG, k = e % DEG;
        int nb = dst[ids[a]*DEG + k];
        #pragma unroll
        for (int b = 0; b < S; b++) {
            if (ids[b] == nb) { atomicOr(&smask[a], 1u << b); atomicOr(&smask[b], 1u << a); }
        }
    }
    __syncthreads();
    if (tid < S) smask[tid] &= ~(1u << tid);
    __syncthreads();

    const float alpha = g_alpha;
    const float oma = 1.0f - alpha;
    const float cE = (1.0f/EPS) * LOG2E;
    const float c3 = 4.0f * alpha * (1.0f/EPS) * LOG2E;
    const float m2a = -2.0f * alpha;

    int t = tid >> 5, lane = tid & 31;
    bool rowact = lane < S;
    int i = rowact ? lane : 0;
    unsigned mask_i = rowact ? smask[i] : 0u;
    float hc1 = __popc(mask_i) * (1.0f / S);
    unsigned extra = (lane == 0 || !rowact) ? 0u : (mask_i & ~1u);

    // outer-invariant exponent base; F recovered from Earg at the end
    float Earg[MN], Fbase;
    {
        int id = ids[i];
        float xs = g_xsq[id];
        const float2* pm2 = (const float2*)(g_Pm + (size_t)id*TM + t*MN);
        float pmv[MN];
        #pragma unroll
        for (int h = 0; h < 5; h++) { float2 p = __ldg(&pm2[h]); pmv[2*h] = p.x; pmv[2*h+1] = p.y; }
        float M0 = xs + sF2[t][0] + pmv[0];
        Fbase = oma * M0;
        #pragma unroll
        for (int l = 0; l < MN; l++) {
            float Ml = xs + sF2[t][l] + pmv[l];
            float hh = hc1 + shC2[t][l];
            Earg[l] = rowact ? (oma*(M0 - Ml) - 2.f*alpha*hh) * cE : -1000.f;
        }
    }
    float qcol = __ldg(&g_q[t*MN + (lane < MN ? lane : 0)]);

    float K[MN];
    float w = rowact ? (1.0f / S) : 0.f;
    #pragma unroll
    for (int l = 0; l < MN; l++) K[l] = rowact ? __ldg(&g_q[t*MN + l]) : 0.f;
    if (lane < MN) vbuf[t][lane] = 1.0f;
    __syncwarp();

    for (int it = 0; it <= N_OUTER; it++) {
        // ---- A phase: only H0 is needed (col-marginal identity) ----
        float vv[MN];
        {
            float4 a0 = *(const float4*)&vbuf[t][0];
            float4 a1 = *(const float4*)&vbuf[t][4];
            float2 a2 = *(const float2*)&vbuf[t][8];
            vv[0]=a0.x; vv[1]=a0.y; vv[2]=a0.z; vv[3]=a0.w;
            vv[4]=a1.x; vv[5]=a1.y; vv[6]=a1.z; vv[7]=a1.w;
            vv[8]=a2.x; vv[9]=a2.y;
        }
        float g[MN];
        #pragma unroll
        for (int l = 0; l < MN; l++) g[l] = K[l] * w * vv[l];
        if (lane == 0) {
            *(float4*)&gbuf[t][0] = make_float4(g[0],g[1],g[2],g[3]);
            *(float4*)&gbuf[t][4] = make_float4(g[4],g[5],g[6],g[7]);
            *(float2*)&gbuf[t][8] = make_float2(g[8],g[9]);
        }
        __syncwarp();
        {
            int l = lane < MN ? lane : 0;
            float4 c0 = *(const float4*)&sC2[t][l][0];
            float4 c1 = *(const float4*)&sC2[t][l][4];
            float2 c2 = *(const float2*)&sC2[t][l][8];
            float4 b0 = *(const float4*)&gbuf[t][0];
            float4 b1 = *(const float4*)&gbuf[t][4];
            float2 b2 = *(const float2*)&gbuf[t][8];
            float h = b0.x*c0.x + b0.y*c0.y + b0.z*c0.z + b0.w*c0.w
                    + b1.x*c1.x + b1.y*c1.y + b1.z*c1.z + b1.w*c1.w
                    + b2.x*c2.x + b2.y*c2.y;
            if (lane < MN) h0buf[t][lane] = h;
        }
        __syncwarp();
        float A[MN];
        {
            float4 a0 = *(const float4*)&h0buf[t][0];
            float4 a1 = *(const float4*)&h0buf[t][4];
            float2 a2 = *(const float2*)&h0buf[t][8];
            A[0]=a0.x; A[1]=a0.y; A[2]=a0.z; A[3]=a0.w;
            A[4]=a1.x; A[5]=a1.y; A[6]=a1.z; A[7]=a1.w;
            A[8]=a2.x; A[9]=a2.y;
        }
        if (lane == 0) {
            #pragma unroll
            for (int l = 0; l < MN; l++) A[l] = sHq[t][l] - A[l];
        }
        unsigned ex = extra;
        while (__any_sync(FULLMASK, ex)) {
            bool has = (ex != 0u);
            int j = has ? (__ffs(ex) - 1) : 0;
            ex &= ex - 1u;
            float wj = __shfl_sync(FULLMASK, w, j);
            float gj[MN];
            #pragma unroll
            for (int k = 0; k < MN; k++) gj[k] = __shfl_sync(FULLMASK, K[k], j) * wj * vv[k];
            #pragma unroll
            for (int l = 0; l < MN; l++) {
                float4 c0 = *(const float4*)&sC2[t][l][0];
                float4 c1 = *(const float4*)&sC2[t][l][4];
                float2 c2 = *(const float2*)&sC2[t][l][8];
                float hj = gj[0]*c0.x + gj[1]*c0.y + gj[2]*c0.z + gj[3]*c0.w
                         + gj[4]*c1.x + gj[5]*c1.y + gj[6]*c1.z + gj[7]*c1.w
                         + gj[8]*c2.x + gj[9]*c2.y;
                if (has) A[l] += hj;
            }
        }

        if (it == N_OUTER) {
            float acc = 0.f;
            #pragma unroll
            for (int l = 0; l < MN; l++) {
                float hh = hc1 + shC2[t][l];
                float Fl = Fbase - Earg[l] * (1.0f/cE) - alpha * hh;
                acc += g[l] * fmaf(m2a, A[l], Fl);
            }
            acc += __shfl_xor_sync(FULLMASK, acc, 16);
            acc += __shfl_xor_sync(FULLMASK, acc, 8);
            acc += __shfl_xor_sync(FULLMASK, acc, 4);
            acc += __shfl_xor_sync(FULLMASK, acc, 2);
            acc += __shfl_xor_sync(FULLMASK, acc, 1);
            if (lane == 0) out[n*T + t] = acc;
            return;
        }

        // ---- K update (row-shifted kernel) + transpose + Sinkhorn ----
        #pragma unroll
        for (int l = 0; l < MN; l++) K[l] = ex2(fmaf(c3, A[l], Earg[l]));
        if (rowact) {
            #pragma unroll
            for (int l = 0; l < MN; l++) ktbuf[t][l][lane] = K[l];
        }
        if (lane < MN) vbuf[t][lane] = 1.0f;
        __syncwarp();

        #pragma unroll
        for (int si = 0; si < N_SINK; si++) {
            // row phase (lanes < S): rs = K . v
            float4 a0 = *(const float4*)&vbuf[t][0];
            float4 a1 = *(const float4*)&vbuf[t][4];
            float2 a2 = *(const float2*)&vbuf[t][8];
            float rs = K[0]*a0.x + K[1]*a0.y + K[2]*a0.z + K[3]*a0.w
                     + K[4]*a1.x + K[5]*a1.y + K[6]*a1.z + K[7]*a1.w
                     + K[8]*a2.x + K[9]*a2.y;
            w = rowact ? __fdividef(1.0f / S, rs) : 0.f;
            if (rowact) wbuf[t][lane] = w;
            __syncwarp();
            // col phase (lanes < MN): cs = KT[l] . w
            {
                int l = lane < MN ? lane : 0;
                float4 w0 = *(const float4*)&wbuf[t][0];
                float4 w1 = *(const float4*)&wbuf[t][4];
                float4 w2 = *(const float4*)&wbuf[t][8];
                float4 w3 = *(const float4*)&wbuf[t][12];
                float  w4 = wbuf[t][16];
                float4 k0 = *(const float4*)&ktbuf[t][l][0];
                float4 k1 = *(const float4*)&ktbuf[t][l][4];
                float4 k2 = *(const float4*)&ktbuf[t][l][8];
                float4 k3 = *(const float4*)&ktbuf[t][l][12];
                float  k4 = ktbuf[t][l][16];
                float cs = k0.x*w0.x + k0.y*w0.y + k0.z*w0.z + k0.w*w0.w
                         + k1.x*w1.x + k1.y*w1.y + k1.z*w1.z + k1.w*w1.w
                         + k2.x*w2.x + k2.y*w2.y + k2.z*w2.z + k2.w*w2.w
                         + k3.x*w3.x + k3.y*w3.y + k3.z*w3.z + k3.w*w3.w
                         + k4*w4;
                if (lane < MN) vbuf[t][lane] = __fdividef(qcol, cs);
            }
            __syncwarp();
        }
    }
}

// ---------------- launch ----------------------------------------------------
extern "C" void kernel_launch(void* const* d_in, const int* in_sizes, int n_in,
                              void* d_out, int out_size) {
    const float* x      = (const float*)d_in[0];
    const int*   edge   = (const int*)  d_in[1];
    const float* tmpl   = (const float*)d_in[2];
    const float* tf     = (const float*)d_in[3];
    const float* q0     = (const float*)d_in[4];
    const float* alpha0 = (const float*)d_in[5];
    const int*   dst    = edge + N_NODES*DEG;
    float* out = (float*)d_out;

    pm_pre_kernel<<<N_NODES/NPB, 256>>>(x, tf, tmpl, q0, alpha0);
    ltfgw_kernel<<<N_NODES, 320>>>(dst, out);
}